// round 12
// baseline (speedup 1.0000x reference)
#include <cuda_runtime.h>
#include <math.h>

// ---------------- problem constants ----------------
#define BATCH   32
#define CCH     256
#define HH      56
#define HW      3136            // 56*56
#define CHW     802816          // CCH*HW
#define TOTAL   25690112        // BATCH*CHW
#define NCHUNK  16
#define CHUNKN  6272            // elements per (channel,chunk) = 2*HW
#define KWRD    64              // 256 / 4 packed words

// ---------------- scratch (no allocation allowed) ----------------
__device__ float g_h1[TOTAL];
__device__ float g_h2[TOTAL];            // also aliased as packed uint8 code buffer
__device__ float g_psmin[8192];
__device__ float g_psmax[8192];
__device__ float g_scal[16];             // 0/1 x, 2/3 h1, 4/5 h2, 6/7 h3, 8/9 scw/mnw
__device__ float g_qdw[CCH * 9];
__device__ float g_qdb[CCH];
__device__ unsigned g_wc[CCH * KWRD];    // packed pw weight codes [co][kword]
__device__ int   g_S3[CCH];              // sum of weight codes per co
__device__ float g_cmin[CCH * NCHUNK];
__device__ float g_cmax[CCH * NCHUNK];
__device__ double g_csum[CCH * NCHUNK];
__device__ float g_mean[CCH], g_qsc[CCH], g_qwt[CCH];

// ---------------- helpers ----------------
// t = d / sc computed as recip-multiply + one Newton step (== div.rn up to ~1 ulp ties)
__device__ __forceinline__ float qdiv(float d, float sc, float inv) {
    float t0 = __fmul_rn(d, inv);
    float r  = __fmaf_rn(t0, -sc, d);
    return __fmaf_rn(r, inv, t0);
}
__device__ __forceinline__ float qz_val(float v, float mn, float sc, float inv) {
    float t = qdiv(__fsub_rn(v, mn), sc, inv);
    t = fminf(fmaxf(t, 0.0f), 255.0f);
    float n = rintf(t);
    return __fadd_rn(__fmul_rn(n, sc), mn);
}
__device__ __forceinline__ int qz_code(float v, float mn, float sc, float inv) {
    float t = qdiv(__fsub_rn(v, mn), sc, inv);
    t = fminf(fmaxf(t, 0.0f), 255.0f);
    return (int)rintf(t);
}
__device__ __forceinline__ float mk_scale(float mn, float mx) {
    return fmaxf(__fdiv_rn(__fsub_rn(mx, mn), 255.0f), 1e-8f);
}

__device__ __forceinline__ void red_minmax(float& mn, float& mx, float* shn, float* shx) {
    int t = threadIdx.x, n = blockDim.x;
    shn[t] = mn; shx[t] = mx; __syncthreads();
    for (int s = n >> 1; s > 0; s >>= 1) {
        if (t < s) { shn[t] = fminf(shn[t], shn[t + s]); shx[t] = fmaxf(shx[t], shx[t + s]); }
        __syncthreads();
    }
    mn = shn[0]; mx = shx[0]; __syncthreads();
}

// ---------------- per-sample min/max of x (raw) ----------------
__global__ void k_psminmax_x(const float* __restrict__ x) {
    int blk = blockIdx.x;                // b*64 + part
    const float* base = x + (size_t)blk * 12544;
    float mn = 1e30f, mx = -1e30f;
    for (int i = threadIdx.x; i < 12544; i += 256) {
        float v = base[i]; mn = fminf(mn, v); mx = fmaxf(mx, v);
    }
    __shared__ float shn[256], shx[256];
    red_minmax(mn, mx, shn, shx);
    if (threadIdx.x == 0) { g_psmin[blk] = mn; g_psmax[blk] = mx; }
}

// combine: mean over batch of per-sample min/max (sequential sum like ref)
__global__ void k_combine(int slot, int ppb) {
    __shared__ float smn[32], smx[32];
    int t = threadIdx.x;                 // 32 threads, one per sample
    float mn = 1e30f, mx = -1e30f;
    for (int i = 0; i < ppb; i++) {
        mn = fminf(mn, g_psmin[t * ppb + i]);
        mx = fmaxf(mx, g_psmax[t * ppb + i]);
    }
    smn[t] = mn; smx[t] = mx; __syncthreads();
    if (t == 0) {
        float sn = 0.0f, sx = 0.0f;
        for (int b = 0; b < BATCH; b++) { sn = __fadd_rn(sn, smn[b]); sx = __fadd_rn(sx, smx[b]); }
        g_scal[slot]     = __fmul_rn(sn, 0.03125f);
        g_scal[slot + 1] = __fmul_rn(sx, 0.03125f);
    }
}

// ---------------- depthwise weight/bias quantization ----------------
__global__ void k_dw_wparams(const float* __restrict__ w, const float* __restrict__ b) {
    __shared__ float shn[256], shx[256];
    int t = threadIdx.x;
    float mn = 1e30f, mx = -1e30f;
    for (int i = t; i < CCH * 9; i += 256) { float v = w[i]; mn = fminf(mn, v); mx = fmaxf(mx, v); }
    red_minmax(mn, mx, shn, shx);
    float sc = mk_scale(mn, mx);
    for (int i = t; i < CCH * 9; i += 256) {
        float tt = __fdiv_rn(__fsub_rn(w[i], mn), sc);
        tt = fminf(fmaxf(tt, 0.0f), 255.0f);
        g_qdw[i] = __fadd_rn(__fmul_rn(rintf(tt), sc), mn);
    }
    float v = b[t];
    float bmn = v, bmx = v;
    red_minmax(bmn, bmx, shn, shx);
    float bsc = mk_scale(bmn, bmx);
    float tt = __fdiv_rn(__fsub_rn(v, bmn), bsc);
    tt = fminf(fmaxf(tt, 0.0f), 255.0f);
    g_qdb[t] = __fadd_rn(__fmul_rn(rintf(tt), bsc), bmn);
}

// ---------------- pointwise weight codes + S3 ----------------
__global__ void k_pw_wparams(const float* __restrict__ w) {
    __shared__ float shn[256], shx[256];
    int t = threadIdx.x;
    float mn = 1e30f, mx = -1e30f;
    for (int i = t; i < CCH * CCH; i += 256) { float v = w[i]; mn = fminf(mn, v); mx = fmaxf(mx, v); }
    red_minmax(mn, mx, shn, shx);
    float sc = mk_scale(mn, mx);
    int co = t;
    int s3 = 0;
    for (int g = 0; g < KWRD; g++) {
        unsigned word = 0;
#pragma unroll
        for (int j = 0; j < 4; j++) {
            float tt = __fdiv_rn(__fsub_rn(w[co * CCH + g * 4 + j], mn), sc);
            tt = fminf(fmaxf(tt, 0.0f), 255.0f);
            int n = (int)rintf(tt);
            s3 += n;
            word |= ((unsigned)n) << (8 * j);
        }
        g_wc[co * KWRD + g] = word;
    }
    g_S3[co] = s3;
    if (t == 0) { g_scal[8] = sc; g_scal[9] = mn; }
}

// ---------------- depthwise conv (tiled, inline quantize) + fused out-minmax ----------------
__global__ void __launch_bounds__(256) k_dwconv(const float* __restrict__ x) {
    __shared__ float qt[58 * 58];
    int blk = blockIdx.x;                // b*256 + c
    int c = blk & 255;
    int t = threadIdx.x;
    float mn = g_scal[0], mx = g_scal[1];
    float sc = mk_scale(mn, mx), inv = 1.0f / sc;
    const float* xp = x + (size_t)blk * HW;
    for (int i = t; i < 58 * 58; i += 256) {
        int hh = i / 58 - 1, ww = i % 58 - 1;
        float v = 0.0f;
        if ((unsigned)hh < HH && (unsigned)ww < HH)
            v = qz_val(xp[hh * HH + ww], mn, sc, inv);
        qt[i] = v;
    }
    __syncthreads();
    float wq[9];
#pragma unroll
    for (int i = 0; i < 9; i++) wq[i] = g_qdw[c * 9 + i];
    float bq = g_qdb[c];
    float omn = 1e30f, omx = -1e30f;
    float* outp = g_h1 + (size_t)blk * HW;
    for (int o = t; o < HW; o += 256) {
        int h = o / HH, w = o % HH;
        const float* q0 = &qt[h * 58 + w];
        float acc = 0.0f;
#pragma unroll
        for (int kh = 0; kh < 3; kh++)
#pragma unroll
            for (int kw = 0; kw < 3; kw++)
                acc = __fmaf_rn(q0[kh * 58 + kw], wq[kh * 3 + kw], acc);
        acc = __fadd_rn(acc, bq);
        outp[o] = acc;
        omn = fminf(omn, acc); omx = fmaxf(omx, acc);
    }
    __shared__ float shn[256], shx[256];
    red_minmax(omn, omx, shn, shx);
    if (t == 0) { g_psmin[blk] = omn; g_psmax[blk] = omx; }
}

// ---------------- per-(channel, chunk) stats; materializes quantized values to g_h2 ----------------
__global__ void __launch_bounds__(256) k_chunk_stats(int slot) {
    int blk = blockIdx.x;                // c*16 + ch
    int c = blk >> 4, ch = blk & 15;
    float mn = g_scal[slot], mx = g_scal[slot + 1];
    float sc = mk_scale(mn, mx), inv = 1.0f / sc;
    float vmn = 1e30f, vmx = -1e30f;
    double vs = 0.0;
    for (int i = threadIdx.x; i < 2 * HW; i += 256) {
        int half = (i >= HW);
        int b = ch * 2 + half;
        int off = i - half * HW;
        size_t idx = (size_t)(b * CCH + c) * HW + off;
        float q = qz_val(g_h1[idx], mn, sc, inv);
        g_h2[idx] = q;
        vmn = fminf(vmn, q); vmx = fmaxf(vmx, q); vs += (double)q;
    }
    __shared__ float shn[256], shx[256];
    __shared__ double shd[256];
    red_minmax(vmn, vmx, shn, shx);
    int t = threadIdx.x;
    shd[t] = vs; __syncthreads();
    for (int s = 128; s > 0; s >>= 1) { if (t < s) shd[t] += shd[t + s]; __syncthreads(); }
    if (t == 0) { g_cmin[blk] = vmn; g_cmax[blk] = vmx; g_csum[blk] = shd[0]; }
}

// ---------------- RangeBN per-channel params ----------------
__global__ void k_bn_params(const float* __restrict__ bnw) {
    __shared__ float shn[256], shx[256];
    int c = threadIdx.x;
    float mmax = 0.0f, mmin = 0.0f;
    double sum = 0.0;
    for (int k = 0; k < NCHUNK; k++) {
        mmax = __fadd_rn(mmax, g_cmax[c * NCHUNK + k]);
        mmin = __fadd_rn(mmin, g_cmin[c * NCHUNK + k]);
        sum += g_csum[c * NCHUNK + k];
    }
    mmax = __fmul_rn(mmax, 0.0625f);
    mmin = __fmul_rn(mmin, 0.0625f);
    float mean = (float)(sum / 100352.0);
    const float sfix = (float)(0.175 * (1.0 + sqrt(3.14159265358979323846 * log(4.0)))
                               / sqrt(2.0 * log((double)CHUNKN)));
    float scale = __fdiv_rn(1.0f, __fadd_rn(__fmul_rn(__fsub_rn(mmax, mmin), sfix), 1e-5f));
    // quantize scale vector (per-tensor over 256 channels)
    float smn = scale, smx = scale;
    red_minmax(smn, smx, shn, shx);
    float ssc = mk_scale(smn, smx);
    float ts = __fdiv_rn(__fsub_rn(scale, smn), ssc);
    ts = fminf(fmaxf(ts, 0.0f), 255.0f);
    float qs = __fadd_rn(__fmul_rn(rintf(ts), ssc), smn);
    // quantize bn weight
    float w = bnw[c];
    float wmn = w, wmx = w;
    red_minmax(wmn, wmx, shn, shx);
    float wsc = mk_scale(wmn, wmx);
    float tw = __fdiv_rn(__fsub_rn(w, wmn), wsc);
    tw = fminf(fmaxf(tw, 0.0f), 255.0f);
    float qw = __fadd_rn(__fmul_rn(rintf(tw), wsc), wmn);
    g_mean[c] = mean; g_qsc[c] = qs; g_qwt[c] = qw;
}

// ---------------- BN apply + ReLU, ref op order; optional fused minmax ----------------
// to_ext selects destination INSIDE device code (never pass a __device__ symbol from host!)
__global__ void k_bn_apply(const float* __restrict__ bnb, float* __restrict__ ext, int to_ext) {
    int blk = blockIdx.x;                // b*64 + part
    int part = blk & 63;
    size_t base = (size_t)blk * 12544;
    float* dst = to_ext ? ext : g_h1;
    float omn = 1e30f, omx = -1e30f;
    for (int i = threadIdx.x; i < 12544; i += 256) {
        int c = part * 4 + i / HW;       // 12544 = 4 channel-planes
        float q = g_h2[base + i];
        float o = __fmul_rn(__fsub_rn(q, g_mean[c]), g_qsc[c]);
        o = __fmul_rn(o, g_qwt[c]);
        o = __fadd_rn(o, bnb[c]);
        o = fmaxf(o, 0.0f);
        dst[base + i] = o;
        omn = fminf(omn, o); omx = fmaxf(omx, o);
    }
    if (!to_ext) {
        __shared__ float shn[256], shx[256];
        red_minmax(omn, omx, shn, shx);
        if (threadIdx.x == 0) { g_psmin[blk] = omn; g_psmax[blk] = omx; }
    }
}

// ---------------- X codes: quantize h2 (g_h1) -> packed transposed codes in g_h2 ----------------
__global__ void __launch_bounds__(256) k_xcodes() {
    __shared__ unsigned char sm[64 * 68];
    int nt = blockIdx.x;                 // 0..48 (n tile)
    int ct = blockIdx.y;                 // 0..3  (ci tile of 64)
    int b  = blockIdx.z;
    int t = threadIdx.x;
    float mn = g_scal[4], mx = g_scal[5];
    float sc = mk_scale(mn, mx), inv = 1.0f / sc;
    int nl = t & 63;
    int cb = t >> 6;                     // 0..3
    for (int r = 0; r < 16; r++) {
        int cl = cb + r * 4;             // 0..63
        float v = g_h1[(size_t)(b * CCH + ct * 64 + cl) * HW + nt * 64 + nl];
        sm[cl * 68 + nl] = (unsigned char)qz_code(v, mn, sc, inv);
    }
    __syncthreads();
    unsigned* Xp = (unsigned*)g_h2;
    for (int j = 0; j < 4; j++) {
        int widx = t + j * 256;
        int n_local = widx >> 4;         // 0..63
        int wi = widx & 15;              // 0..15
        unsigned w = (unsigned)sm[(wi * 4 + 0) * 68 + n_local]
                   | ((unsigned)sm[(wi * 4 + 1) * 68 + n_local] << 8)
                   | ((unsigned)sm[(wi * 4 + 2) * 68 + n_local] << 16)
                   | ((unsigned)sm[(wi * 4 + 3) * 68 + n_local] << 24);
        Xp[(size_t)(b * HW + nt * 64 + n_local) * KWRD + ct * 16 + wi] = w;
    }
}

// ---------------- pointwise GEMM via exact-integer dp4a + fused out-minmax ----------------
// Static smem only (< 48 KB): X tile resident (64 px * 64 words = 16 KB),
// W streamed in 4 groups of 64 co (16 KB each). Thread computes 16 co x 4 px.
__global__ void __launch_bounds__(256) k_pwgemm() {
    __shared__ unsigned Xs[64 * KWRD];   // 16 KB
    __shared__ unsigned Ws[64 * KWRD];   // 16 KB
    __shared__ unsigned s2[64];
    __shared__ float shn[256], shx[256];

    int nt = blockIdx.x, b = blockIdx.y;
    int t = threadIdx.x;
    const unsigned* Xp = (const unsigned*)g_h2;

    const unsigned* xsrc = Xp + (size_t)(b * HW + nt * 64) * KWRD;
    for (int i = t; i < 64 * KWRD; i += 256) Xs[i] = xsrc[i];
    __syncthreads();
    if (t < 64) {
        unsigned s = 0;
        for (int k = 0; k < KWRD; k++) s = __dp4a(Xs[t * KWRD + k], 0x01010101u, s);
        s2[t] = s;
    }

    int co_sub = (t >> 4) << 2;          // 0,4,...,60 within each 64-co group
    int n_base = (t & 15) << 2;          // 0,4,...,60
    unsigned acc[16][4];
#pragma unroll
    for (int i = 0; i < 16; i++)
#pragma unroll
        for (int j = 0; j < 4; j++) acc[i][j] = 0u;

    for (int cg = 0; cg < 4; cg++) {
        __syncthreads();
        for (int i = t; i < 64 * KWRD; i += 256) Ws[i] = g_wc[cg * 64 * KWRD + i];
        __syncthreads();
        for (int k = 0; k < KWRD; k += 4) {
            uint4 xv[4];
#pragma unroll
            for (int j = 0; j < 4; j++) xv[j] = *(const uint4*)&Xs[(n_base + j) * KWRD + k];
#pragma unroll
            for (int r = 0; r < 4; r++) {
                uint4 wv = *(const uint4*)&Ws[(co_sub + r) * KWRD + k];
                int ai = cg * 4 + r;
#pragma unroll
                for (int j = 0; j < 4; j++) {
                    acc[ai][j] = __dp4a(wv.x, xv[j].x, acc[ai][j]);
                    acc[ai][j] = __dp4a(wv.y, xv[j].y, acc[ai][j]);
                    acc[ai][j] = __dp4a(wv.z, xv[j].z, acc[ai][j]);
                    acc[ai][j] = __dp4a(wv.w, xv[j].w, acc[ai][j]);
                }
            }
        }
    }

    float mnx = g_scal[4];
    float scx = mk_scale(mnx, g_scal[5]);
    float scw = g_scal[8], mnw = g_scal[9];
    double d1 = (double)scx * (double)scw;
    double d2 = (double)scx * (double)mnw;
    double d3 = (double)mnx * (double)scw;
    double d4 = 256.0 * (double)mnx * (double)mnw;

    float omn = 1e30f, omx = -1e30f;
    float* outb = g_h1 + (size_t)b * CHW + nt * 64 + n_base;
#pragma unroll
    for (int cg = 0; cg < 4; cg++) {
#pragma unroll
        for (int r = 0; r < 4; r++) {
            int co = cg * 64 + co_sub + r;
            float4 ov;
            float* o = (float*)&ov;
#pragma unroll
            for (int j = 0; j < 4; j++) {
                double v = (double)acc[cg * 4 + r][j] * d1 + (double)s2[n_base + j] * d2
                         + (double)g_S3[co] * d3 + d4;
                float f = (float)v;
                o[j] = f;
                omn = fminf(omn, f); omx = fmaxf(omx, f);
            }
            *(float4*)(outb + (size_t)co * HW) = ov;
        }
    }

    red_minmax(omn, omx, shn, shx);
    if (t == 0) { g_psmin[b * 49 + nt] = omn; g_psmax[b * 49 + nt] = omx; }
}

// ---------------- launch ----------------
extern "C" void kernel_launch(void* const* d_in, const int* in_sizes, int n_in,
                              void* d_out, int out_size) {
    const float* x    = (const float*)d_in[0];
    const float* dww  = (const float*)d_in[1];
    const float* dwb  = (const float*)d_in[2];
    const float* bn1w = (const float*)d_in[3];
    const float* bn1b = (const float*)d_in[4];
    const float* pww  = (const float*)d_in[5];
    const float* bn2w = (const float*)d_in[6];
    const float* bn2b = (const float*)d_in[7];
    float* out = (float*)d_out;

    // Stage 1: quant_measure(x) + depthwise conv (fused output minmax)
    k_psminmax_x<<<2048, 256>>>(x);
    k_combine<<<1, 32>>>(0, 64);
    k_dw_wparams<<<1, 256>>>(dww, dwb);
    k_pw_wparams<<<1, 256>>>(pww);
    k_dwconv<<<BATCH * CCH, 256>>>(x);

    // Stage 2: range_bn #1 (quantized h1 -> g_h2, BN+ReLU -> g_h1 internally), fused h2 minmax
    k_combine<<<1, 32>>>(2, 256);
    k_chunk_stats<<<CCH * NCHUNK, 256>>>(2);
    k_bn_params<<<1, 256>>>(bn1w);
    k_bn_apply<<<2048, 256>>>(bn1b, out, 0);   // to_ext=0 -> writes g_h1 (device-side select)

    // Stage 3: quantize h2 -> packed codes, exact-int GEMM -> g_h1 (fused minmax)
    k_combine<<<1, 32>>>(4, 64);
    k_xcodes<<<dim3(49, 4, BATCH), 256>>>();
    k_pwgemm<<<dim3(49, BATCH), 256>>>();

    // Stage 4: range_bn #2 -> d_out
    k_combine<<<1, 32>>>(6, 49);
    k_chunk_stats<<<CCH * NCHUNK, 256>>>(6);
    k_bn_params<<<1, 256>>>(bn2w);
    k_bn_apply<<<2048, 256>>>(bn2b, out, 1);   // to_ext=1 -> writes d_out
}

// round 13
// speedup vs baseline: 1.8325x; 1.8325x over previous
#include <cuda_runtime.h>
#include <math.h>

// ---------------- problem constants ----------------
#define BATCH   32
#define CCH     256
#define HH      56
#define HW      3136            // 56*56
#define CHW     802816          // CCH*HW
#define TOTAL   25690112        // BATCH*CHW
#define NCHUNK  16
#define CHUNKN  6272            // elements per (channel,chunk) = 2*HW
#define KWRD    64              // 256 / 4 packed words

// ---------------- scratch (no allocation allowed) ----------------
__device__ float g_h1[TOTAL];
__device__ float g_h2[TOTAL];            // aliased: uint8 chunk codes / packed GEMM codes
__device__ float g_psmin[8192];
__device__ float g_psmax[8192];
__device__ float g_scal[16];             // 0/1 x, 2/3 h1, 4/5 h2, 6/7 h3, 8/9 scw/mnw
__device__ float g_qdw[CCH * 9];
__device__ float g_qdb[CCH];
__device__ unsigned g_wc[CCH * KWRD];    // packed pw weight codes, SIGNED (n^0x80), [co][kword]
__device__ int   g_S3[CCH];              // sum of UNSIGNED weight codes per co
__device__ float g_cmin[CCH * NCHUNK];
__device__ float g_cmax[CCH * NCHUNK];
__device__ double g_csum[CCH * NCHUNK];
__device__ float g_mean[CCH], g_qsc[CCH], g_qwt[CCH];

// ---------------- helpers ----------------
// t = d / sc via recip-multiply + one Newton step (== div.rn up to rare 1-ulp ties)
__device__ __forceinline__ float qdiv(float d, float sc, float inv) {
    float t0 = __fmul_rn(d, inv);
    float r  = __fmaf_rn(t0, -sc, d);
    return __fmaf_rn(r, inv, t0);
}
__device__ __forceinline__ float qz_val(float v, float mn, float sc, float inv) {
    float t = qdiv(__fsub_rn(v, mn), sc, inv);
    t = fminf(fmaxf(t, 0.0f), 255.0f);
    float n = rintf(t);
    return __fadd_rn(__fmul_rn(n, sc), mn);
}
__device__ __forceinline__ int qz_code(float v, float mn, float sc, float inv) {
    float t = qdiv(__fsub_rn(v, mn), sc, inv);
    t = fminf(fmaxf(t, 0.0f), 255.0f);
    return (int)rintf(t);
}
__device__ __forceinline__ float mk_scale(float mn, float mx) {
    return fmaxf(__fdiv_rn(__fsub_rn(mx, mn), 255.0f), 1e-8f);
}

__device__ __forceinline__ void red_minmax(float& mn, float& mx, float* shn, float* shx) {
    int t = threadIdx.x, n = blockDim.x;
    shn[t] = mn; shx[t] = mx; __syncthreads();
    for (int s = n >> 1; s > 0; s >>= 1) {
        if (t < s) { shn[t] = fminf(shn[t], shn[t + s]); shx[t] = fmaxf(shx[t], shx[t + s]); }
        __syncthreads();
    }
    mn = shn[0]; mx = shx[0]; __syncthreads();
}

// int8 tensor-core mma: D(16x8,s32) += A(16x32,s8,row) * B(32x8,s8,col)
__device__ __forceinline__ void mma_s8(int& c0, int& c1, int& c2, int& c3,
                                       unsigned a0, unsigned a1, unsigned a2, unsigned a3,
                                       unsigned b0, unsigned b1) {
    asm volatile(
        "mma.sync.aligned.m16n8k32.row.col.s32.s8.s8.s32 "
        "{%0,%1,%2,%3}, {%4,%5,%6,%7}, {%8,%9}, {%0,%1,%2,%3};"
        : "+r"(c0), "+r"(c1), "+r"(c2), "+r"(c3)
        : "r"(a0), "r"(a1), "r"(a2), "r"(a3), "r"(b0), "r"(b1));
}

// ---------------- per-sample min/max of x (raw) ----------------
__global__ void k_psminmax_x(const float* __restrict__ x) {
    int blk = blockIdx.x;                // b*64 + part
    const float4* base = (const float4*)(x + (size_t)blk * 12544);
    float mn = 1e30f, mx = -1e30f;
    for (int i = threadIdx.x; i < 3136; i += 256) {
        float4 v = base[i];
        mn = fminf(mn, fminf(fminf(v.x, v.y), fminf(v.z, v.w)));
        mx = fmaxf(mx, fmaxf(fmaxf(v.x, v.y), fmaxf(v.z, v.w)));
    }
    __shared__ float shn[256], shx[256];
    red_minmax(mn, mx, shn, shx);
    if (threadIdx.x == 0) { g_psmin[blk] = mn; g_psmax[blk] = mx; }
}

// combine: mean over batch of per-sample min/max (sequential sum like ref)
__global__ void k_combine(int slot, int ppb) {
    __shared__ float smn[32], smx[32];
    int t = threadIdx.x;                 // 32 threads, one per sample
    float mn = 1e30f, mx = -1e30f;
    for (int i = 0; i < ppb; i++) {
        mn = fminf(mn, g_psmin[t * ppb + i]);
        mx = fmaxf(mx, g_psmax[t * ppb + i]);
    }
    smn[t] = mn; smx[t] = mx; __syncthreads();
    if (t == 0) {
        float sn = 0.0f, sx = 0.0f;
        for (int b = 0; b < BATCH; b++) { sn = __fadd_rn(sn, smn[b]); sx = __fadd_rn(sx, smx[b]); }
        g_scal[slot]     = __fmul_rn(sn, 0.03125f);
        g_scal[slot + 1] = __fmul_rn(sx, 0.03125f);
    }
}

// ---------------- depthwise weight/bias quantization ----------------
__global__ void k_dw_wparams(const float* __restrict__ w, const float* __restrict__ b) {
    __shared__ float shn[256], shx[256];
    int t = threadIdx.x;
    float mn = 1e30f, mx = -1e30f;
    for (int i = t; i < CCH * 9; i += 256) { float v = w[i]; mn = fminf(mn, v); mx = fmaxf(mx, v); }
    red_minmax(mn, mx, shn, shx);
    float sc = mk_scale(mn, mx);
    for (int i = t; i < CCH * 9; i += 256) {
        float tt = __fdiv_rn(__fsub_rn(w[i], mn), sc);
        tt = fminf(fmaxf(tt, 0.0f), 255.0f);
        g_qdw[i] = __fadd_rn(__fmul_rn(rintf(tt), sc), mn);
    }
    float v = b[t];
    float bmn = v, bmx = v;
    red_minmax(bmn, bmx, shn, shx);
    float bsc = mk_scale(bmn, bmx);
    float tt = __fdiv_rn(__fsub_rn(v, bmn), bsc);
    tt = fminf(fmaxf(tt, 0.0f), 255.0f);
    g_qdb[t] = __fadd_rn(__fmul_rn(rintf(tt), bsc), bmn);
}

// ---------------- pointwise weight: parallel minmax then pack ----------------
__global__ void k_pw_mm1(const float* __restrict__ w) {
    int blk = blockIdx.x;                // 64 blocks, 1024 elems each
    const float* base = w + blk * 1024;
    float mn = 1e30f, mx = -1e30f;
    for (int i = threadIdx.x; i < 1024; i += 256) {
        float v = base[i]; mn = fminf(mn, v); mx = fmaxf(mx, v);
    }
    __shared__ float shn[256], shx[256];
    red_minmax(mn, mx, shn, shx);
    if (threadIdx.x == 0) { g_psmin[4096 + blk] = mn; g_psmax[4096 + blk] = mx; }
}

__global__ void k_pw_pack(const float* __restrict__ w) {
    // every block deterministically reduces the 64 partials
    float mn = 1e30f, mx = -1e30f;
    for (int i = 0; i < 64; i++) {
        mn = fminf(mn, g_psmin[4096 + i]);
        mx = fmaxf(mx, g_psmax[4096 + i]);
    }
    float sc = mk_scale(mn, mx);
    int t = threadIdx.x;
    int co = blockIdx.x * 4 + (t >> 6);  // 4 co rows per block
    int kw = t & 63;
    __shared__ int s3sh[4];
    if (t < 4) s3sh[t] = 0;
    __syncthreads();
    unsigned word = 0;
    int s3 = 0;
#pragma unroll
    for (int j = 0; j < 4; j++) {
        float tt = __fdiv_rn(__fsub_rn(w[co * CCH + kw * 4 + j], mn), sc);
        tt = fminf(fmaxf(tt, 0.0f), 255.0f);
        int n = (int)rintf(tt);
        s3 += n;
        word |= ((unsigned)n) << (8 * j);
    }
    g_wc[co * KWRD + kw] = word ^ 0x80808080u;   // store signed-offset codes
    atomicAdd(&s3sh[t >> 6], s3);
    __syncthreads();
    if (t < 4) g_S3[blockIdx.x * 4 + t] = s3sh[t];
    if (blockIdx.x == 0 && t == 0) { g_scal[8] = sc; g_scal[9] = mn; }
}

// ---------------- depthwise conv (tiled, inline quantize) + fused out-minmax ----------------
__global__ void __launch_bounds__(256) k_dwconv(const float* __restrict__ x) {
    __shared__ float qt[58 * 58];
    int blk = blockIdx.x;                // b*256 + c
    int c = blk & 255;
    int t = threadIdx.x;
    float mn = g_scal[0], mx = g_scal[1];
    float sc = mk_scale(mn, mx), inv = 1.0f / sc;
    const float* xp = x + (size_t)blk * HW;
    for (int i = t; i < 58 * 58; i += 256) {
        int hh = i / 58 - 1, ww = i % 58 - 1;
        float v = 0.0f;
        if ((unsigned)hh < HH && (unsigned)ww < HH)
            v = qz_val(xp[hh * HH + ww], mn, sc, inv);
        qt[i] = v;
    }
    __syncthreads();
    float wq[9];
#pragma unroll
    for (int i = 0; i < 9; i++) wq[i] = g_qdw[c * 9 + i];
    float bq = g_qdb[c];
    float omn = 1e30f, omx = -1e30f;
    float* outp = g_h1 + (size_t)blk * HW;
    for (int o = t; o < HW; o += 256) {
        int h = o / HH, w = o % HH;
        const float* q0 = &qt[h * 58 + w];
        float acc = 0.0f;
#pragma unroll
        for (int kh = 0; kh < 3; kh++)
#pragma unroll
            for (int kw = 0; kw < 3; kw++)
                acc = __fmaf_rn(q0[kh * 58 + kw], wq[kh * 3 + kw], acc);
        acc = __fadd_rn(acc, bq);
        outp[o] = acc;
        omn = fminf(omn, acc); omx = fmaxf(omx, acc);
    }
    __shared__ float shn[256], shx[256];
    red_minmax(omn, omx, shn, shx);
    if (t == 0) { g_psmin[blk] = omn; g_psmax[blk] = omx; }
}

// ---------------- per-(channel, chunk) stats; writes uint8 codes to g_h2 ----------------
__global__ void __launch_bounds__(256) k_chunk_stats(int slot) {
    int blk = blockIdx.x;                // c*16 + ch
    int c = blk >> 4, ch = blk & 15;
    float mn = g_scal[slot], mx = g_scal[slot + 1];
    float sc = mk_scale(mn, mx), inv = 1.0f / sc;
    unsigned char* gc = (unsigned char*)g_h2;
    float vmn = 1e30f, vmx = -1e30f;
    double vs = 0.0;
    for (int i = threadIdx.x * 4; i < 2 * HW; i += 1024) {
        int half = (i >= HW);
        int b = ch * 2 + half;
        int off = i - half * HW;
        size_t idx = (size_t)(b * CCH + c) * HW + off;
        float4 v = *(const float4*)&g_h1[idx];
        float q0 = qz_val(v.x, mn, sc, inv);
        float q1 = qz_val(v.y, mn, sc, inv);
        float q2 = qz_val(v.z, mn, sc, inv);
        float q3 = qz_val(v.w, mn, sc, inv);
        uchar4 cd;
        cd.x = (unsigned char)qz_code(v.x, mn, sc, inv);
        cd.y = (unsigned char)qz_code(v.y, mn, sc, inv);
        cd.z = (unsigned char)qz_code(v.z, mn, sc, inv);
        cd.w = (unsigned char)qz_code(v.w, mn, sc, inv);
        *(uchar4*)&gc[idx] = cd;
        vmn = fminf(vmn, fminf(fminf(q0, q1), fminf(q2, q3)));
        vmx = fmaxf(vmx, fmaxf(fmaxf(q0, q1), fmaxf(q2, q3)));
        vs += (double)q0 + (double)q1 + (double)q2 + (double)q3;
    }
    __shared__ float shn[256], shx[256];
    __shared__ double shd[256];
    red_minmax(vmn, vmx, shn, shx);
    int t = threadIdx.x;
    shd[t] = vs; __syncthreads();
    for (int s = 128; s > 0; s >>= 1) { if (t < s) shd[t] += shd[t + s]; __syncthreads(); }
    if (t == 0) { g_cmin[blk] = vmn; g_cmax[blk] = vmx; g_csum[blk] = shd[0]; }
}

// ---------------- RangeBN per-channel params ----------------
__global__ void k_bn_params(const float* __restrict__ bnw) {
    __shared__ float shn[256], shx[256];
    int c = threadIdx.x;
    float mmax = 0.0f, mmin = 0.0f;
    double sum = 0.0;
    for (int k = 0; k < NCHUNK; k++) {
        mmax = __fadd_rn(mmax, g_cmax[c * NCHUNK + k]);
        mmin = __fadd_rn(mmin, g_cmin[c * NCHUNK + k]);
        sum += g_csum[c * NCHUNK + k];
    }
    mmax = __fmul_rn(mmax, 0.0625f);
    mmin = __fmul_rn(mmin, 0.0625f);
    float mean = (float)(sum / 100352.0);
    const float sfix = (float)(0.175 * (1.0 + sqrt(3.14159265358979323846 * log(4.0)))
                               / sqrt(2.0 * log((double)CHUNKN)));
    float scale = __fdiv_rn(1.0f, __fadd_rn(__fmul_rn(__fsub_rn(mmax, mmin), sfix), 1e-5f));
    float smn = scale, smx = scale;
    red_minmax(smn, smx, shn, shx);
    float ssc = mk_scale(smn, smx);
    float ts = __fdiv_rn(__fsub_rn(scale, smn), ssc);
    ts = fminf(fmaxf(ts, 0.0f), 255.0f);
    float qs = __fadd_rn(__fmul_rn(rintf(ts), ssc), smn);
    float w = bnw[c];
    float wmn = w, wmx = w;
    red_minmax(wmn, wmx, shn, shx);
    float wsc = mk_scale(wmn, wmx);
    float tw = __fdiv_rn(__fsub_rn(w, wmn), wsc);
    tw = fminf(fmaxf(tw, 0.0f), 255.0f);
    float qw = __fadd_rn(__fmul_rn(rintf(tw), wsc), wmn);
    g_mean[c] = mean; g_qsc[c] = qs; g_qwt[c] = qw;
}

// ---------------- BN apply + ReLU from uint8 codes, ref op order ----------------
__global__ void k_bn_apply(const float* __restrict__ bnb, float* __restrict__ ext,
                           int to_ext, int slot) {
    int blk = blockIdx.x;                // b*64 + part (part = 4 channel-planes)
    int part = blk & 63;
    size_t base = (size_t)blk * 12544;
    float mn = g_scal[slot], mx = g_scal[slot + 1];
    float sc = mk_scale(mn, mx);
    const unsigned char* gc = (const unsigned char*)g_h2;
    float* dst = to_ext ? ext : g_h1;
    float omn = 1e30f, omx = -1e30f;
    for (int w = threadIdx.x; w < 3136; w += 256) {
        int c = part * 4 + w / 784;      // 784 words (3136 elems) per channel
        uchar4 cd = *(const uchar4*)&gc[base + (size_t)w * 4];
        float mean = g_mean[c], qs = g_qsc[c], qw = g_qwt[c], bb = bnb[c];
        float4 ov;
        float q, o;
        q = __fadd_rn(__fmul_rn((float)cd.x, sc), mn);
        o = __fmul_rn(__fmul_rn(__fsub_rn(q, mean), qs), qw); o = fmaxf(__fadd_rn(o, bb), 0.0f); ov.x = o;
        q = __fadd_rn(__fmul_rn((float)cd.y, sc), mn);
        o = __fmul_rn(__fmul_rn(__fsub_rn(q, mean), qs), qw); o = fmaxf(__fadd_rn(o, bb), 0.0f); ov.y = o;
        q = __fadd_rn(__fmul_rn((float)cd.z, sc), mn);
        o = __fmul_rn(__fmul_rn(__fsub_rn(q, mean), qs), qw); o = fmaxf(__fadd_rn(o, bb), 0.0f); ov.z = o;
        q = __fadd_rn(__fmul_rn((float)cd.w, sc), mn);
        o = __fmul_rn(__fmul_rn(__fsub_rn(q, mean), qs), qw); o = fmaxf(__fadd_rn(o, bb), 0.0f); ov.w = o;
        *(float4*)&dst[base + (size_t)w * 4] = ov;
        omn = fminf(omn, fminf(fminf(ov.x, ov.y), fminf(ov.z, ov.w)));
        omx = fmaxf(omx, fmaxf(fmaxf(ov.x, ov.y), fmaxf(ov.z, ov.w)));
    }
    if (!to_ext) {
        __shared__ float shn[256], shx[256];
        red_minmax(omn, omx, shn, shx);
        if (threadIdx.x == 0) { g_psmin[blk] = omn; g_psmax[blk] = omx; }
    }
}

// ---------------- X codes: quantize h2 (g_h1) -> packed SIGNED transposed codes in g_h2 ----
__global__ void __launch_bounds__(256) k_xcodes() {
    __shared__ unsigned char sm[64 * 68];
    int nt = blockIdx.x;                 // 0..48 (n tile)
    int ct = blockIdx.y;                 // 0..3  (ci tile of 64)
    int b  = blockIdx.z;
    int t = threadIdx.x;
    float mn = g_scal[4], mx = g_scal[5];
    float sc = mk_scale(mn, mx), inv = 1.0f / sc;
    int nl = t & 63;
    int cb = t >> 6;                     // 0..3
    for (int r = 0; r < 16; r++) {
        int cl = cb + r * 4;             // 0..63
        float v = g_h1[(size_t)(b * CCH + ct * 64 + cl) * HW + nt * 64 + nl];
        sm[cl * 68 + nl] = (unsigned char)qz_code(v, mn, sc, inv);
    }
    __syncthreads();
    unsigned* Xp = (unsigned*)g_h2;
    for (int j = 0; j < 4; j++) {
        int widx = t + j * 256;
        int n_local = widx >> 4;         // 0..63
        int wi = widx & 15;              // 0..15
        unsigned w = (unsigned)sm[(wi * 4 + 0) * 68 + n_local]
                   | ((unsigned)sm[(wi * 4 + 1) * 68 + n_local] << 8)
                   | ((unsigned)sm[(wi * 4 + 2) * 68 + n_local] << 16)
                   | ((unsigned)sm[(wi * 4 + 3) * 68 + n_local] << 24);
        Xp[(size_t)(b * HW + nt * 64 + n_local) * KWRD + ct * 16 + wi] = w ^ 0x80808080u;
    }
}

// ---------------- pointwise GEMM: int8 tensor-core mma, exact integer result ----------------
// Tile per block: 256 co x 64 px, K=256. Codes stored signed-offset (n-128); corrections
// via S2 (px code sums) and S3 (co code sums) reconstruct the exact unsigned product.
// 8 warps: warp = (coFrag cf in {0..3} of 16 rows) x (px half in {0,1} of 32 px).
__global__ void __launch_bounds__(256) k_pwgemm() {
    __shared__ unsigned Xs[64 * 68];     // [px][kword], pad 68 for conflict-free mma feeds
    __shared__ unsigned Ws[64 * 68];     // [co_local][kword]
    __shared__ int s2s[64];              // signed code sums per px
    __shared__ int s3sh[64];             // unsigned code sums per co_local
    __shared__ float shn[256], shx[256];

    int nt = blockIdx.x, b = blockIdx.y;
    int t = threadIdx.x;
    const unsigned* Xp = (const unsigned*)g_h2;
    const unsigned* xsrc = Xp + (size_t)(b * HW + nt * 64) * KWRD;
    for (int i = t; i < 64 * 64; i += 256) Xs[(i >> 6) * 68 + (i & 63)] = xsrc[i];
    __syncthreads();
    if (t < 64) {
        int s = 0;
        for (int k = 0; k < 64; k++) s = __dp4a((int)Xs[t * 68 + k], 0x01010101, s);
        s2s[t] = s;                      // sum of signed codes (n-128)
    }

    int lane = t & 31, wp = t >> 5;
    int cf  = (wp & 3) * 16;             // co frag base within 64-co group
    int pxb = (wp >> 2) * 32;            // px base (covers 4 px-frags of 8)
    int grp = lane >> 2, qd = lane & 3;

    float mnx = g_scal[4];
    float scx = mk_scale(mnx, g_scal[5]);
    float scw = g_scal[8], mnw = g_scal[9];
    float d1 = (float)((double)scx * (double)scw);
    float d2 = (float)((double)scx * (double)mnw);
    float d3 = (float)((double)mnx * (double)scw);
    float d4 = (float)(256.0 * (double)mnx * (double)mnw);

    float omn = 1e30f, omx = -1e30f;
    float* outb = g_h1 + (size_t)b * CHW + nt * 64;

    for (int cg = 0; cg < 4; cg++) {
        __syncthreads();
        for (int i = t; i < 64 * 64; i += 256) Ws[(i >> 6) * 68 + (i & 63)] = g_wc[cg * 64 * 64 + i];
        if (t < 64) s3sh[t] = g_S3[cg * 64 + t];
        __syncthreads();

        int acc[4][4];
#pragma unroll
        for (int pf = 0; pf < 4; pf++)
#pragma unroll
            for (int j = 0; j < 4; j++) acc[pf][j] = 0;

#pragma unroll
        for (int ks = 0; ks < 8; ks++) {
            unsigned a0 = Ws[(cf + grp) * 68 + ks * 8 + qd];
            unsigned a1 = Ws[(cf + grp + 8) * 68 + ks * 8 + qd];
            unsigned a2 = Ws[(cf + grp) * 68 + ks * 8 + 4 + qd];
            unsigned a3 = Ws[(cf + grp + 8) * 68 + ks * 8 + 4 + qd];
#pragma unroll
            for (int pf = 0; pf < 4; pf++) {
                unsigned b0 = Xs[(pxb + pf * 8 + grp) * 68 + ks * 8 + qd];
                unsigned b1 = Xs[(pxb + pf * 8 + grp) * 68 + ks * 8 + 4 + qd];
                mma_s8(acc[pf][0], acc[pf][1], acc[pf][2], acc[pf][3], a0, a1, a2, a3, b0, b1);
            }
        }

        // epilogue for this 64-co group
        int s3a = s3sh[cf + grp];                  // co = cg*64+cf+grp
        int s3b = s3sh[cf + grp + 8];              // co + 8
        float f3a = __fmaf_rn((float)s3a, d3, d4);
        float f3b = __fmaf_rn((float)s3b, d3, d4);
        int co0 = cg * 64 + cf + grp;
#pragma unroll
        for (int pf = 0; pf < 4; pf++) {
            int px0 = pxb + pf * 8 + qd * 2;
            int s2a = s2s[px0]     + 32768;        // unsigned code sum
            int s2b = s2s[px0 + 1] + 32768;
            float f2a = __fmaf_rn((float)s2a, d2, f3a);
            float f2b = __fmaf_rn((float)s2b, d2, f3a);
            float f2a2 = __fmaf_rn((float)s2a, d2, f3b);
            float f2b2 = __fmaf_rn((float)s2b, d2, f3b);
            // exact unsigned product: R = M + 128*(S3+S2) - 128*128*256
            int R00 = acc[pf][0] + 128 * (s3a + s2a) - 4194304;
            int R01 = acc[pf][1] + 128 * (s3a + s2b) - 4194304;
            int R10 = acc[pf][2] + 128 * (s3b + s2a) - 4194304;
            int R11 = acc[pf][3] + 128 * (s3b + s2b) - 4194304;
            float v00 = __fmaf_rn((float)R00, d1, f2a);
            float v01 = __fmaf_rn((float)R01, d1, f2b);
            float v10 = __fmaf_rn((float)R10, d1, f2a2);
            float v11 = __fmaf_rn((float)R11, d1, f2b2);
            *(float2*)(outb + (size_t)co0 * HW + px0)       = make_float2(v00, v01);
            *(float2*)(outb + (size_t)(co0 + 8) * HW + px0) = make_float2(v10, v11);
            omn = fminf(omn, fminf(fminf(v00, v01), fminf(v10, v11)));
            omx = fmaxf(omx, fmaxf(fmaxf(v00, v01), fmaxf(v10, v11)));
        }
    }

    red_minmax(omn, omx, shn, shx);
    if (t == 0) { g_psmin[b * 49 + nt] = omn; g_psmax[b * 49 + nt] = omx; }
}

// ---------------- launch ----------------
extern "C" void kernel_launch(void* const* d_in, const int* in_sizes, int n_in,
                              void* d_out, int out_size) {
    const float* x    = (const float*)d_in[0];
    const float* dww  = (const float*)d_in[1];
    const float* dwb  = (const float*)d_in[2];
    const float* bn1w = (const float*)d_in[3];
    const float* bn1b = (const float*)d_in[4];
    const float* pww  = (const float*)d_in[5];
    const float* bn2w = (const float*)d_in[6];
    const float* bn2b = (const float*)d_in[7];
    float* out = (float*)d_out;

    // Stage 1: quant_measure(x) + weight prep + depthwise conv (fused out-minmax)
    k_psminmax_x<<<2048, 256>>>(x);
    k_combine<<<1, 32>>>(0, 64);
    k_dw_wparams<<<1, 256>>>(dww, dwb);
    k_pw_mm1<<<64, 256>>>(pww);
    k_pw_pack<<<64, 256>>>(pww);
    k_dwconv<<<BATCH * CCH, 256>>>(x);

    // Stage 2: range_bn #1 — codes to g_h2, BN+ReLU to g_h1 (device-side dst select)
    k_combine<<<1, 32>>>(2, 256);
    k_chunk_stats<<<CCH * NCHUNK, 256>>>(2);
    k_bn_params<<<1, 256>>>(bn1w);
    k_bn_apply<<<2048, 256>>>(bn1b, out, 0, 2);

    // Stage 3: quantize h2 -> packed signed codes, tensor-core GEMM -> g_h1 (fused minmax)
    k_combine<<<1, 32>>>(4, 64);
    k_xcodes<<<dim3(49, 4, BATCH), 256>>>();
    k_pwgemm<<<dim3(49, BATCH), 256>>>();

    // Stage 4: range_bn #2 -> d_out
    k_combine<<<1, 32>>>(6, 49);
    k_chunk_stats<<<CCH * NCHUNK, 256>>>(6);
    k_bn_params<<<1, 256>>>(bn2w);
    k_bn_apply<<<2048, 256>>>(bn2b, out, 1, 6);
}

// round 16
// speedup vs baseline: 1.9313x; 1.0539x over previous
#include <cuda_runtime.h>
#include <math.h>

// ---------------- problem constants ----------------
#define BATCH   32
#define CCH     256
#define HH      56
#define HW      3136            // 56*56
#define CHW     802816          // CCH*HW
#define TOTAL   25690112        // BATCH*CHW
#define NCHUNK  16
#define CHUNKN  6272            // elements per (channel,chunk) = 2*HW
#define KWRD    64              // 256 / 4 packed words

// ---------------- scratch (no allocation allowed) ----------------
__device__ float g_h1[TOTAL];
__device__ float g_h2[TOTAL];            // aliased as uint8 chunk-code buffer
__device__ unsigned g_xc[TOTAL / 4];     // packed signed GEMM codes [b][px][kword] (dedicated!)
__device__ float g_psmin[8192];
__device__ float g_psmax[8192];
__device__ float g_scal[16];             // 0/1 x, 2/3 h1, 4/5 h2, 6/7 h3, 8/9 scw/mnw
__device__ float g_qdw[CCH * 9];
__device__ float g_qdb[CCH];
__device__ unsigned g_wc[CCH * KWRD];    // packed pw weight codes, SIGNED (n^0x80), [co][kword]
__device__ int   g_S3[CCH];              // sum of UNSIGNED weight codes per co
__device__ float g_cmin[CCH * NCHUNK];
__device__ float g_cmax[CCH * NCHUNK];
__device__ double g_csum[CCH * NCHUNK];
__device__ float g_qbmin[CCH * BATCH];   // per (c,b) min of quantized h1 values
__device__ float g_qbmax[CCH * BATCH];
__device__ float g_mean[CCH], g_qsc[CCH], g_qwt[CCH];

// ---------------- helpers ----------------
__device__ __forceinline__ float qdiv(float d, float sc, float inv) {
    float t0 = __fmul_rn(d, inv);
    float r  = __fmaf_rn(t0, -sc, d);
    return __fmaf_rn(r, inv, t0);        // == div.rn up to rare 1-ulp ties
}
__device__ __forceinline__ float qz_val(float v, float mn, float sc, float inv) {
    float t = qdiv(__fsub_rn(v, mn), sc, inv);
    t = fminf(fmaxf(t, 0.0f), 255.0f);
    float n = rintf(t);
    return __fadd_rn(__fmul_rn(n, sc), mn);
}
__device__ __forceinline__ int qz_code(float v, float mn, float sc, float inv) {
    float t = qdiv(__fsub_rn(v, mn), sc, inv);
    t = fminf(fmaxf(t, 0.0f), 255.0f);
    return (int)rintf(t);
}
__device__ __forceinline__ float mk_scale(float mn, float mx) {
    return fmaxf(__fdiv_rn(__fsub_rn(mx, mn), 255.0f), 1e-8f);
}
__device__ __forceinline__ void red_minmax(float& mn, float& mx, float* shn, float* shx) {
    int t = threadIdx.x, n = blockDim.x;
    shn[t] = mn; shx[t] = mx; __syncthreads();
    for (int s = n >> 1; s > 0; s >>= 1) {
        if (t < s) { shn[t] = fminf(shn[t], shn[t + s]); shx[t] = fmaxf(shx[t], shx[t + s]); }
        __syncthreads();
    }
    mn = shn[0]; mx = shx[0]; __syncthreads();
}
// BN chain exactly as applied elementwise (monotone in q)
__device__ __forceinline__ float bn_chain(float q, float mean, float qs, float qw, float bb) {
    float o = __fmul_rn(__fmul_rn(__fsub_rn(q, mean), qs), qw);
    return fmaxf(__fadd_rn(o, bb), 0.0f);
}

// int8 tensor-core mma: D(16x8,s32) += A(16x32,s8,row) * B(32x8,s8,col)
__device__ __forceinline__ void mma_s8(int& c0, int& c1, int& c2, int& c3,
                                       unsigned a0, unsigned a1, unsigned a2, unsigned a3,
                                       unsigned b0, unsigned b1) {
    asm volatile(
        "mma.sync.aligned.m16n8k32.row.col.s32.s8.s8.s32 "
        "{%0,%1,%2,%3}, {%4,%5,%6,%7}, {%8,%9}, {%0,%1,%2,%3};"
        : "+r"(c0), "+r"(c1), "+r"(c2), "+r"(c3)
        : "r"(a0), "r"(a1), "r"(a2), "r"(a3), "r"(b0), "r"(b1));
}

// ---------------- scan: per-sample minmax of x (2048 blocks) + pw weight partials (64) ----
__global__ void k_scan(const float* __restrict__ x, const float* __restrict__ pww) {
    __shared__ float shn[256], shx[256];
    int blk = blockIdx.x;
    float mn = 1e30f, mx = -1e30f;
    if (blk < 2048) {
        const float4* base = (const float4*)(x + (size_t)blk * 12544);
        for (int i = threadIdx.x; i < 3136; i += 256) {
            float4 v = base[i];
            mn = fminf(mn, fminf(fminf(v.x, v.y), fminf(v.z, v.w)));
            mx = fmaxf(mx, fmaxf(fmaxf(v.x, v.y), fmaxf(v.z, v.w)));
        }
        red_minmax(mn, mx, shn, shx);
        if (threadIdx.x == 0) { g_psmin[blk] = mn; g_psmax[blk] = mx; }
    } else {
        const float* base = pww + (blk - 2048) * 1024;
        for (int i = threadIdx.x; i < 1024; i += 256) {
            float v = base[i]; mn = fminf(mn, v); mx = fmaxf(mx, v);
        }
        red_minmax(mn, mx, shn, shx);
        if (threadIdx.x == 0) { g_psmin[4096 + blk - 2048] = mn; g_psmax[4096 + blk - 2048] = mx; }
    }
}

// combine: mean over batch of per-sample min/max (sequential sum like ref)
__global__ void k_combine(int slot, int ppb) {
    __shared__ float smn[32], smx[32];
    int t = threadIdx.x;                 // 32 threads
    float mn = 1e30f, mx = -1e30f;
    for (int i = 0; i < ppb; i++) {
        mn = fminf(mn, g_psmin[t * ppb + i]);
        mx = fmaxf(mx, g_psmax[t * ppb + i]);
    }
    smn[t] = mn; smx[t] = mx; __syncthreads();
    if (t == 0) {
        float sn = 0.0f, sx = 0.0f;
        for (int b = 0; b < BATCH; b++) { sn = __fadd_rn(sn, smn[b]); sx = __fadd_rn(sx, smx[b]); }
        g_scal[slot]     = __fmul_rn(sn, 0.03125f);
        g_scal[slot + 1] = __fmul_rn(sx, 0.03125f);
    }
}

// ---------------- prep: blk0 = combine(x), blk1 = dw weights, blk2..65 = pw pack ----------
__global__ void k_prep(const float* __restrict__ dww, const float* __restrict__ dwb,
                       const float* __restrict__ pww) {
    __shared__ float shn[256], shx[256];
    int blk = blockIdx.x;
    int t = threadIdx.x;
    if (blk == 0) {
        __shared__ float smn[32], smx[32];
        if (t < 32) {
            float mn = 1e30f, mx = -1e30f;
            for (int i = 0; i < 64; i++) {
                mn = fminf(mn, g_psmin[t * 64 + i]);
                mx = fmaxf(mx, g_psmax[t * 64 + i]);
            }
            smn[t] = mn; smx[t] = mx;
            __syncwarp();
            if (t == 0) {
                float sn = 0.0f, sx = 0.0f;
                for (int b = 0; b < BATCH; b++) { sn = __fadd_rn(sn, smn[b]); sx = __fadd_rn(sx, smx[b]); }
                g_scal[0] = __fmul_rn(sn, 0.03125f);
                g_scal[1] = __fmul_rn(sx, 0.03125f);
            }
        }
    } else if (blk == 1) {
        float mn = 1e30f, mx = -1e30f;
        for (int i = t; i < CCH * 9; i += 256) { float v = dww[i]; mn = fminf(mn, v); mx = fmaxf(mx, v); }
        red_minmax(mn, mx, shn, shx);
        float sc = mk_scale(mn, mx);
        for (int i = t; i < CCH * 9; i += 256) {
            float tt = __fdiv_rn(__fsub_rn(dww[i], mn), sc);
            tt = fminf(fmaxf(tt, 0.0f), 255.0f);
            g_qdw[i] = __fadd_rn(__fmul_rn(rintf(tt), sc), mn);
        }
        float v = dwb[t];
        float bmn = v, bmx = v;
        red_minmax(bmn, bmx, shn, shx);
        float bsc = mk_scale(bmn, bmx);
        float tt = __fdiv_rn(__fsub_rn(v, bmn), bsc);
        tt = fminf(fmaxf(tt, 0.0f), 255.0f);
        g_qdb[t] = __fadd_rn(__fmul_rn(rintf(tt), bsc), bmn);
    } else {
        float mn = 1e30f, mx = -1e30f;
        for (int i = 0; i < 64; i++) {
            mn = fminf(mn, g_psmin[4096 + i]);
            mx = fmaxf(mx, g_psmax[4096 + i]);
        }
        float sc = mk_scale(mn, mx);
        int grp = blk - 2;
        int co = grp * 4 + (t >> 6);
        int kw = t & 63;
        __shared__ int s3sh[4];
        if (t < 4) s3sh[t] = 0;
        __syncthreads();
        unsigned word = 0;
        int s3 = 0;
#pragma unroll
        for (int j = 0; j < 4; j++) {
            float tt = __fdiv_rn(__fsub_rn(pww[co * CCH + kw * 4 + j], mn), sc);
            tt = fminf(fmaxf(tt, 0.0f), 255.0f);
            int n = (int)rintf(tt);
            s3 += n;
            word |= ((unsigned)n) << (8 * j);
        }
        g_wc[co * KWRD + kw] = word ^ 0x80808080u;
        atomicAdd(&s3sh[t >> 6], s3);
        __syncthreads();
        if (t < 4) g_S3[grp * 4 + t] = s3sh[t];
        if (grp == 0 && t == 0) { g_scal[8] = sc; g_scal[9] = mn; }
    }
}

// ---------------- depthwise conv (tiled, inline quantize) + fused out-minmax ----------------
__global__ void __launch_bounds__(256) k_dwconv(const float* __restrict__ x) {
    __shared__ float qt[58 * 58];
    int blk = blockIdx.x;                // b*256 + c
    int c = blk & 255;
    int t = threadIdx.x;
    float mn = g_scal[0], mx = g_scal[1];
    float sc = mk_scale(mn, mx), inv = 1.0f / sc;
    const float* xp = x + (size_t)blk * HW;
    for (int i = t; i < 58 * 58; i += 256) {
        int hh = i / 58 - 1, ww = i % 58 - 1;
        float v = 0.0f;
        if ((unsigned)hh < HH && (unsigned)ww < HH)
            v = qz_val(xp[hh * HH + ww], mn, sc, inv);
        qt[i] = v;
    }
    __syncthreads();
    float wq[9];
#pragma unroll
    for (int i = 0; i < 9; i++) wq[i] = g_qdw[c * 9 + i];
    float bq = g_qdb[c];
    float omn = 1e30f, omx = -1e30f;
    float* outp = g_h1 + (size_t)blk * HW;
    for (int o = t; o < HW; o += 256) {
        int h = o / HH, w = o % HH;
        const float* q0 = &qt[h * 58 + w];
        float acc = 0.0f;
#pragma unroll
        for (int kh = 0; kh < 3; kh++)
#pragma unroll
            for (int kw = 0; kw < 3; kw++)
                acc = __fmaf_rn(q0[kh * 58 + kw], wq[kh * 3 + kw], acc);
        acc = __fadd_rn(acc, bq);
        outp[o] = acc;
        omn = fminf(omn, acc); omx = fmaxf(omx, acc);
    }
    __shared__ float shn[256], shx[256];
    red_minmax(omn, omx, shn, shx);
    if (t == 0) { g_psmin[blk] = omn; g_psmax[blk] = omx; }
}

// ---------------- per-(channel,chunk) stats + per-(c,b) minmax; writes uint8 codes ----------
__global__ void __launch_bounds__(256) k_chunk_stats(int slot) {
    int blk = blockIdx.x;                // c*16 + ch
    int c = blk >> 4, ch = blk & 15;
    float mn = g_scal[slot], mx = g_scal[slot + 1];
    float sc = mk_scale(mn, mx), inv = 1.0f / sc;
    unsigned char* gc = (unsigned char*)g_h2;
    float mn0 = 1e30f, mx0 = -1e30f, mn1 = 1e30f, mx1 = -1e30f;
    double vs = 0.0;
    for (int i = threadIdx.x * 4; i < 2 * HW; i += 1024) {
        int half = (i >= HW);
        int b = ch * 2 + half;
        int off = i - half * HW;
        size_t idx = (size_t)(b * CCH + c) * HW + off;
        float4 v = *(const float4*)&g_h1[idx];
        float q0 = qz_val(v.x, mn, sc, inv);
        float q1 = qz_val(v.y, mn, sc, inv);
        float q2 = qz_val(v.z, mn, sc, inv);
        float q3 = qz_val(v.w, mn, sc, inv);
        uchar4 cd;
        cd.x = (unsigned char)qz_code(v.x, mn, sc, inv);
        cd.y = (unsigned char)qz_code(v.y, mn, sc, inv);
        cd.z = (unsigned char)qz_code(v.z, mn, sc, inv);
        cd.w = (unsigned char)qz_code(v.w, mn, sc, inv);
        *(uchar4*)&gc[idx] = cd;
        float lmn = fminf(fminf(q0, q1), fminf(q2, q3));
        float lmx = fmaxf(fmaxf(q0, q1), fmaxf(q2, q3));
        if (half) { mn1 = fminf(mn1, lmn); mx1 = fmaxf(mx1, lmx); }
        else      { mn0 = fminf(mn0, lmn); mx0 = fmaxf(mx0, lmx); }
        vs += (double)q0 + (double)q1 + (double)q2 + (double)q3;
    }
    __shared__ float shn[256], shx[256];
    __shared__ double shd[256];
    red_minmax(mn0, mx0, shn, shx);
    red_minmax(mn1, mx1, shn, shx);
    int t = threadIdx.x;
    shd[t] = vs; __syncthreads();
    for (int s = 128; s > 0; s >>= 1) { if (t < s) shd[t] += shd[t + s]; __syncthreads(); }
    if (t == 0) {
        g_cmin[blk] = fminf(mn0, mn1);
        g_cmax[blk] = fmaxf(mx0, mx1);
        g_csum[blk] = shd[0];
        int b0 = ch * 2;
        g_qbmin[c * BATCH + b0] = mn0;  g_qbmax[c * BATCH + b0] = mx0;
        g_qbmin[c * BATCH + b0 + 1] = mn1;  g_qbmax[c * BATCH + b0 + 1] = mx1;
    }
}

// ---------------- RangeBN params (+ optional analytic h2 minmax -> slot 4/5) --------------
__global__ void k_bn_params(const float* __restrict__ bnw, const float* __restrict__ bnb,
                            int do_h2) {
    __shared__ float shn[256], shx[256];
    int c = threadIdx.x;
    float mmax = 0.0f, mmin = 0.0f;
    double sum = 0.0;
    for (int k = 0; k < NCHUNK; k++) {
        mmax = __fadd_rn(mmax, g_cmax[c * NCHUNK + k]);
        mmin = __fadd_rn(mmin, g_cmin[c * NCHUNK + k]);
        sum += g_csum[c * NCHUNK + k];
    }
    mmax = __fmul_rn(mmax, 0.0625f);
    mmin = __fmul_rn(mmin, 0.0625f);
    float mean = (float)(sum / 100352.0);
    const float sfix = (float)(0.175 * (1.0 + sqrt(3.14159265358979323846 * log(4.0)))
                               / sqrt(2.0 * log((double)CHUNKN)));
    float scale = __fdiv_rn(1.0f, __fadd_rn(__fmul_rn(__fsub_rn(mmax, mmin), sfix), 1e-5f));
    float smn = scale, smx = scale;
    red_minmax(smn, smx, shn, shx);
    float ssc = mk_scale(smn, smx);
    float ts = __fdiv_rn(__fsub_rn(scale, smn), ssc);
    ts = fminf(fmaxf(ts, 0.0f), 255.0f);
    float qs = __fadd_rn(__fmul_rn(rintf(ts), ssc), smn);
    float w = bnw[c];
    float wmn = w, wmx = w;
    red_minmax(wmn, wmx, shn, shx);
    float wsc = mk_scale(wmn, wmx);
    float tw = __fdiv_rn(__fsub_rn(w, wmn), wsc);
    tw = fminf(fmaxf(tw, 0.0f), 255.0f);
    float qw = __fadd_rn(__fmul_rn(rintf(tw), wsc), wmn);
    g_mean[c] = mean; g_qsc[c] = qs; g_qwt[c] = qw;

    if (!do_h2) return;
    __syncthreads();
    // analytic per-sample min/max of h2 (monotone BN chain => exact from q endpoints)
    __shared__ float sbmn[32], sbmx[32];
    int t = threadIdx.x;
    int b = t >> 3, g = t & 7;           // 32 samples x 8 channel-groups
    float emn = 1e30f, emx = -1e30f;
    for (int cc = 0; cc < 32; cc++) {
        int ci = g * 32 + cc;
        float mm = g_mean[ci], qq = g_qsc[ci], ww2 = g_qwt[ci], bb = bnb[ci];
        float o1 = bn_chain(g_qbmin[ci * BATCH + b], mm, qq, ww2, bb);
        float o2 = bn_chain(g_qbmax[ci * BATCH + b], mm, qq, ww2, bb);
        emn = fminf(emn, fminf(o1, o2));
        emx = fmaxf(emx, fmaxf(o1, o2));
    }
#pragma unroll
    for (int o = 4; o > 0; o >>= 1) {
        emn = fminf(emn, __shfl_down_sync(0xffffffffu, emn, o, 8));
        emx = fmaxf(emx, __shfl_down_sync(0xffffffffu, emx, o, 8));
    }
    if (g == 0) { sbmn[b] = emn; sbmx[b] = emx; }
    __syncthreads();
    if (t == 0) {
        float sn = 0.0f, sx = 0.0f;
        for (int bb2 = 0; bb2 < BATCH; bb2++) { sn = __fadd_rn(sn, sbmn[bb2]); sx = __fadd_rn(sx, sbmx[bb2]); }
        g_scal[4] = __fmul_rn(sn, 0.03125f);
        g_scal[5] = __fmul_rn(sx, 0.03125f);
    }
}

// ---------------- fused BN+ReLU+quantize+pack: g_h2 codes -> g_xc packed signed codes ----
__global__ void __launch_bounds__(256) k_bnfuse(const float* __restrict__ bnb) {
    __shared__ unsigned char sm[64 * 256];   // [px][c]
    int nt = blockIdx.x, b = blockIdx.y;
    int c = threadIdx.x;
    float mn2 = g_scal[2], sc2 = mk_scale(mn2, g_scal[3]);
    float mn4 = g_scal[4], sc4 = mk_scale(mn4, g_scal[5]);
    float inv4 = 1.0f / sc4;
    float mean = g_mean[c], qs = g_qsc[c], qw = g_qwt[c], bb = bnb[c];
    const unsigned char* gc = (const unsigned char*)g_h2;
    size_t src = (size_t)(b * CCH + c) * HW + nt * 64;
#pragma unroll
    for (int j16 = 0; j16 < 4; j16++) {
        uint4 v = *(const uint4*)&gc[src + j16 * 16];
        const unsigned char* pb = (const unsigned char*)&v;
#pragma unroll
        for (int jj = 0; jj < 16; jj++) {
            float q = __fadd_rn(__fmul_rn((float)pb[jj], sc2), mn2);
            float o = bn_chain(q, mean, qs, qw, bb);
            sm[(j16 * 16 + jj) * 256 + c] = (unsigned char)qz_code(o, mn4, sc4, inv4);
        }
    }
    __syncthreads();
    int t = threadIdx.x;
#pragma unroll
    for (int i = 0; i < 16; i++) {
        int idx = t + i * 256;
        int px = idx >> 6, kw = idx & 63;
        unsigned w = *(const unsigned*)&sm[px * 256 + kw * 4];
        g_xc[(size_t)(b * HW + nt * 64 + px) * KWRD + kw] = w ^ 0x80808080u;
    }
}

// ---------------- BN apply + ReLU from uint8 codes -> d_out (stage 4) --------------------
__global__ void k_bn_apply(const float* __restrict__ bnb, float* __restrict__ ext, int slot) {
    int blk = blockIdx.x;                // b*64 + part (part = 4 channel-planes)
    int part = blk & 63;
    size_t base = (size_t)blk * 12544;
    float mn = g_scal[slot], mx = g_scal[slot + 1];
    float sc = mk_scale(mn, mx);
    const unsigned char* gc = (const unsigned char*)g_h2;
    for (int w = threadIdx.x; w < 3136; w += 256) {
        int c = part * 4 + w / 784;
        uchar4 cd = *(const uchar4*)&gc[base + (size_t)w * 4];
        float mean = g_mean[c], qs = g_qsc[c], qw = g_qwt[c], bb = bnb[c];
        float4 ov;
        ov.x = bn_chain(__fadd_rn(__fmul_rn((float)cd.x, sc), mn), mean, qs, qw, bb);
        ov.y = bn_chain(__fadd_rn(__fmul_rn((float)cd.y, sc), mn), mean, qs, qw, bb);
        ov.z = bn_chain(__fadd_rn(__fmul_rn((float)cd.z, sc), mn), mean, qs, qw, bb);
        ov.w = bn_chain(__fadd_rn(__fmul_rn((float)cd.w, sc), mn), mean, qs, qw, bb);
        *(float4*)&ext[base + (size_t)w * 4] = ov;
    }
}

// ---------------- pointwise GEMM: int8 tensor-core mma, exact integer result ----------------
__global__ void __launch_bounds__(256) k_pwgemm() {
    __shared__ unsigned Xs[64 * 68];
    __shared__ unsigned Ws[64 * 68];
    __shared__ int s2s[64];
    __shared__ int s3sh[64];
    __shared__ float shn[256], shx[256];

    int nt = blockIdx.x, b = blockIdx.y;
    int t = threadIdx.x;
    const unsigned* xsrc = g_xc + (size_t)(b * HW + nt * 64) * KWRD;
    for (int i = t; i < 64 * 64; i += 256) Xs[(i >> 6) * 68 + (i & 63)] = xsrc[i];
    __syncthreads();
    if (t < 64) {
        int s = 0;
        for (int k = 0; k < 64; k++) s = __dp4a((int)Xs[t * 68 + k], 0x01010101, s);
        s2s[t] = s;                      // sum of signed codes (n-128)
    }

    int lane = t & 31, wp = t >> 5;
    int cf  = (wp & 3) * 16;
    int pxb = (wp >> 2) * 32;
    int grp = lane >> 2, qd = lane & 3;

    float mnx = g_scal[4];
    float scx = mk_scale(mnx, g_scal[5]);
    float scw = g_scal[8], mnw = g_scal[9];
    float d1 = (float)((double)scx * (double)scw);
    float d2 = (float)((double)scx * (double)mnw);
    float d3 = (float)((double)mnx * (double)scw);
    float d4 = (float)(256.0 * (double)mnx * (double)mnw);

    float omn = 1e30f, omx = -1e30f;
    float* outb = g_h1 + (size_t)b * CHW + nt * 64;

    for (int cg = 0; cg < 4; cg++) {
        __syncthreads();
        for (int i = t; i < 64 * 64; i += 256) Ws[(i >> 6) * 68 + (i & 63)] = g_wc[cg * 64 * 64 + i];
        if (t < 64) s3sh[t] = g_S3[cg * 64 + t];
        __syncthreads();

        int acc[4][4];
#pragma unroll
        for (int pf = 0; pf < 4; pf++)
#pragma unroll
            for (int j = 0; j < 4; j++) acc[pf][j] = 0;

#pragma unroll
        for (int ks = 0; ks < 8; ks++) {
            unsigned a0 = Ws[(cf + grp) * 68 + ks * 8 + qd];
            unsigned a1 = Ws[(cf + grp + 8) * 68 + ks * 8 + qd];
            unsigned a2 = Ws[(cf + grp) * 68 + ks * 8 + 4 + qd];
            unsigned a3 = Ws[(cf + grp + 8) * 68 + ks * 8 + 4 + qd];
#pragma unroll
            for (int pf = 0; pf < 4; pf++) {
                unsigned b0 = Xs[(pxb + pf * 8 + grp) * 68 + ks * 8 + qd];
                unsigned b1 = Xs[(pxb + pf * 8 + grp) * 68 + ks * 8 + 4 + qd];
                mma_s8(acc[pf][0], acc[pf][1], acc[pf][2], acc[pf][3], a0, a1, a2, a3, b0, b1);
            }
        }

        int s3a = s3sh[cf + grp];
        int s3b = s3sh[cf + grp + 8];
        float f3a = __fmaf_rn((float)s3a, d3, d4);
        float f3b = __fmaf_rn((float)s3b, d3, d4);
        int co0 = cg * 64 + cf + grp;
#pragma unroll
        for (int pf = 0; pf < 4; pf++) {
            int px0 = pxb + pf * 8 + qd * 2;
            int s2a = s2s[px0]     + 32768;
            int s2b = s2s[px0 + 1] + 32768;
            float f2a  = __fmaf_rn((float)s2a, d2, f3a);
            float f2b  = __fmaf_rn((float)s2b, d2, f3a);
            float f2a2 = __fmaf_rn((float)s2a, d2, f3b);
            float f2b2 = __fmaf_rn((float)s2b, d2, f3b);
            int R00 = acc[pf][0] + 128 * (s3a + s2a) - 4194304;
            int R01 = acc[pf][1] + 128 * (s3a + s2b) - 4194304;
            int R10 = acc[pf][2] + 128 * (s3b + s2a) - 4194304;
            int R11 = acc[pf][3] + 128 * (s3b + s2b) - 4194304;
            float v00 = __fmaf_rn((float)R00, d1, f2a);
            float v01 = __fmaf_rn((float)R01, d1, f2b);
            float v10 = __fmaf_rn((float)R10, d1, f2a2);
            float v11 = __fmaf_rn((float)R11, d1, f2b2);
            *(float2*)(outb + (size_t)co0 * HW + px0)       = make_float2(v00, v01);
            *(float2*)(outb + (size_t)(co0 + 8) * HW + px0) = make_float2(v10, v11);
            omn = fminf(omn, fminf(fminf(v00, v01), fminf(v10, v11)));
            omx = fmaxf(omx, fmaxf(fmaxf(v00, v01), fmaxf(v10, v11)));
        }
    }

    red_minmax(omn, omx, shn, shx);
    if (t == 0) { g_psmin[b * 49 + nt] = omn; g_psmax[b * 49 + nt] = omx; }
}

// ---------------- launch ----------------
extern "C" void kernel_launch(void* const* d_in, const int* in_sizes, int n_in,
                              void* d_out, int out_size) {
    const float* x    = (const float*)d_in[0];
    const float* dww  = (const float*)d_in[1];
    const float* dwb  = (const float*)d_in[2];
    const float* bn1w = (const float*)d_in[3];
    const float* bn1b = (const float*)d_in[4];
    const float* pww  = (const float*)d_in[5];
    const float* bn2w = (const float*)d_in[6];
    const float* bn2b = (const float*)d_in[7];
    float* out = (float*)d_out;

    // Stage 1: scans + weight prep + depthwise conv
    k_scan<<<2112, 256>>>(x, pww);
    k_prep<<<66, 256>>>(dww, dwb, pww);
    k_dwconv<<<BATCH * CCH, 256>>>(x);

    // Stage 2: range_bn #1 stats + params + analytic h2 minmax
    k_combine<<<1, 32>>>(2, 256);
    k_chunk_stats<<<CCH * NCHUNK, 256>>>(2);
    k_bn_params<<<1, 256>>>(bn1w, bn1b, 1);

    // Stage 3: fused BN+quantize+pack (g_h2 -> g_xc), tensor-core GEMM -> g_h1
    k_bnfuse<<<dim3(49, BATCH), 256>>>(bn1b);
    k_pwgemm<<<dim3(49, BATCH), 256>>>();

    // Stage 4: range_bn #2 -> d_out
    k_combine<<<1, 32>>>(6, 49);
    k_chunk_stats<<<CCH * NCHUNK, 256>>>(6);
    k_bn_params<<<1, 256>>>(bn2w, bn2b, 0);
    k_bn_apply<<<2048, 256>>>(bn2b, out, 6);
}